// round 6
// baseline (speedup 1.0000x reference)
#include <cuda_runtime.h>
#include <math.h>

#define B 4
#define C 192
#define HEADS 4
#define DH 32
#define HID 128
#define NMEM 4
#define QT 16
#define SQRTC 13.856406460551018f
#define SCALE 0.17677669529663687f

// ---------------- scratch ----------------------------------------------------
__device__ float g_w[B*160*160];
__device__ float g_rowft[B*C*160];
__device__ float g_colft[B*C*160];
__device__ float g_vbr[B*C*160];
__device__ float g_vbc[B*C*160];
__device__ float g_qkv[6][B*HEADS*160*DH];   // ax*3 + {q,k,v}
__device__ float g_hoT[2][B*HID*160];        // [(b*128+hid)*160 + pos]
__device__ float g_E[2][C*HID];
__device__ float g_e[2][C];

// ---------------- K1: fold (blocks 0..47) + pixel sumsq norms (48..367) ------
__global__ void __launch_bounds__(320) k_pre(
        const float* __restrict__ x, const float* __restrict__ Wr,
        const float* __restrict__ Wo, const float* __restrict__ bo) {
    int bi = blockIdx.x;
    int t = threadIdx.x;  // 320
    if (bi < 48) {
        int ax = bi & 1, d0 = (bi >> 1) * 8;
        __shared__ float Wrs[8][192];
        for (int idx = t; idx < 8*192; idx += 320) {
            int j = idx / 192, c = idx % 192;
            Wrs[j][c] = Wr[(d0 + j)*2*C + ax*C + c];
        }
        __syncthreads();
        if (t < 128) {
            float acc[8] = {0,0,0,0,0,0,0,0};
            #pragma unroll 4
            for (int c = 0; c < C; c++) {
                float wo = Wo[c*HID + t];
                #pragma unroll
                for (int j = 0; j < 8; j++) acc[j] += Wrs[j][c] * wo;
            }
            #pragma unroll
            for (int j = 0; j < 8; j++) g_E[ax][(d0 + j)*HID + t] = acc[j];
        }
        if (t >= 312) {
            int j = t - 312; float e = 0.f;
            for (int c = 0; c < C; c++) e += Wrs[j][c] * bo[c];
            g_e[ax][d0 + j] = e;
        }
    } else {
        int pb = bi - 48;           // 0..319 (2 rows each)
        int b = pb / 80, n = (pb % 80) * 2 + t / 160, m = t % 160;
        const float* xp = x + ((size_t)b*C*160 + n)*160 + m;
        float ss = 0.f;
        #pragma unroll 8
        for (int c = 0; c < C; c++) { float v = xp[(size_t)c*25600]; ss += v*v; }
        g_w[(b*160 + n)*160 + m] = SQRTC / fmaxf(sqrtf(ss), 1e-12f);
    }
}

// ---------------- K2: one pass over x -> row_ft, col_ft, vbr, vbc ------------
__global__ void __launch_bounds__(256) k_reduce(const float* __restrict__ x,
                                                const float* __restrict__ gv) {
    int b = blockIdx.x / C, c = blockIdx.x % C;
    int lane = threadIdx.x & 31, warp = threadIdx.x >> 5;   // 8 warps
    const float* xp = x + (size_t)(b*C + c)*25600;
    const float* wp = g_w + b*25600;
    float gvc = gv[c];
    float4 colA = {0,0,0,0}, vrA = {0,0,0,0}, colB = {0,0,0,0}, vrB = {0,0,0,0};
    for (int i = 0; i < 20; i++) {
        int n = warp*20 + i;
        const float4* xp4 = (const float4*)(xp + n*160);
        const float4* wp4 = (const float4*)(wp + n*160);
        float4 xa = xp4[lane], wa = wp4[lane];
        float rs  = xa.x + xa.y + xa.z + xa.w;
        float vcs = xa.x*wa.x + xa.y*wa.y + xa.z*wa.z + xa.w*wa.w;
        colA.x += xa.x; colA.y += xa.y; colA.z += xa.z; colA.w += xa.w;
        vrA.x += xa.x*wa.x; vrA.y += xa.y*wa.y; vrA.z += xa.z*wa.z; vrA.w += xa.w*wa.w;
        if (lane < 8) {
            float4 xb = xp4[32 + lane], wb = wp4[32 + lane];
            rs  += xb.x + xb.y + xb.z + xb.w;
            vcs += xb.x*wb.x + xb.y*wb.y + xb.z*wb.z + xb.w*wb.w;
            colB.x += xb.x; colB.y += xb.y; colB.z += xb.z; colB.w += xb.w;
            vrB.x += xb.x*wb.x; vrB.y += xb.y*wb.y; vrB.z += xb.z*wb.z; vrB.w += xb.w*wb.w;
        }
        #pragma unroll
        for (int o = 16; o; o >>= 1) {
            rs  += __shfl_xor_sync(0xffffffffu, rs,  o);
            vcs += __shfl_xor_sync(0xffffffffu, vcs, o);
        }
        if (!lane) {
            g_rowft[(b*C + c)*160 + n] = rs * (1.0f/160.0f);
            g_vbc  [(b*C + c)*160 + n] = gvc * vcs;
        }
    }
    __shared__ float scol[8][160], svr[8][160];
    *(float4*)&scol[warp][lane*4] = colA;
    *(float4*)&svr [warp][lane*4] = vrA;
    if (lane < 8) {
        *(float4*)&scol[warp][128 + lane*4] = colB;
        *(float4*)&svr [warp][128 + lane*4] = vrB;
    }
    __syncthreads();
    if (threadIdx.x < 160) {
        int m = threadIdx.x;
        float cs = 0.f, vr = 0.f;
        #pragma unroll
        for (int w2 = 0; w2 < 8; w2++) { cs += scol[w2][m]; vr += svr[w2][m]; }
        g_colft[(b*C + c)*160 + m] = cs * (1.0f/160.0f);
        g_vbr  [(b*C + c)*160 + m] = gvc * vr;
    }
}

// ---------------- K3: projections, 16-pos tiles, full K ----------------------
__global__ void __launch_bounds__(256) k_proj(
        const float* __restrict__ Wq, const float* __restrict__ Wk,
        const float* __restrict__ Wv, const float* __restrict__ gq,
        const float* __restrict__ gk) {
    int which = blockIdx.y;
    int p0 = blockIdx.x * 16;     // 40 tiles
    int b = p0 / 160, q0 = p0 % 160;
    const float *src, *W, *gvec = 0;
    float factor = 1.f;
    switch (which) {
        case 0: src=g_rowft; W=Wq; gvec=gq; factor=SCALE*SQRTC; break;
        case 1: src=g_colft; W=Wk; gvec=gk; factor=SQRTC;       break;
        case 2: src=g_vbr;   W=Wv;                               break;
        case 3: src=g_colft; W=Wq; gvec=gq; factor=SCALE*SQRTC; break;
        case 4: src=g_rowft; W=Wk; gvec=gk; factor=SQRTC;       break;
        default:src=g_vbc;   W=Wv;                               break;
    }
    float* out = g_qkv[which];
    __shared__ float Xs[192][17];
    __shared__ __align__(16) float Wsm[32][132];
    __shared__ float red[16][16];
    __shared__ float fs[16];
    int t = threadIdx.x;
    for (int idx = t; idx < 192*16; idx += 256) {
        int c = idx >> 4, p = idx & 15;
        Xs[c][p] = src[(b*C + c)*160 + q0 + p];
    }
    __syncthreads();
    if (gvec) {
        int p = t & 15, cg = t >> 4;   // 16 groups x 12 channels
        float ssp = 0.f;
        #pragma unroll
        for (int c = cg; c < 192; c += 16) { float v = Xs[c][p]; ssp += v*v; }
        red[cg][p] = ssp;
    }
    __syncthreads();
    if (t < 16) {
        if (gvec) {
            float ss = 0.f;
            #pragma unroll
            for (int j = 0; j < 16; j++) ss += red[j][t];
            fs[t] = factor / fmaxf(sqrtf(ss), 1e-12f);
        } else fs[t] = 1.f;
    }
    int d0 = (t & 31) * 4, pl = (t >> 5) * 2;
    float4 acc0 = {0,0,0,0}, acc1 = {0,0,0,0};
    for (int c0 = 0; c0 < 192; c0 += 32) {
        __syncthreads();
        for (int idx = t; idx < 32*128; idx += 256) {
            int dim = idx >> 5, k = idx & 31;
            float wv = W[dim*C + c0 + k];
            if (gvec) wv *= gvec[c0 + k];
            Wsm[k][dim] = wv;
        }
        __syncthreads();
        #pragma unroll
        for (int k = 0; k < 32; k++) {
            float4 wv = *(const float4*)&Wsm[k][d0];
            float x0 = Xs[c0 + k][pl], x1 = Xs[c0 + k][pl + 1];
            acc0.x += wv.x*x0; acc0.y += wv.y*x0; acc0.z += wv.z*x0; acc0.w += wv.w*x0;
            acc1.x += wv.x*x1; acc1.y += wv.y*x1; acc1.z += wv.z*x1; acc1.w += wv.w*x1;
        }
    }
    int h = d0 >> 5, dd = d0 & 31;
    float f0 = fs[pl], f1 = fs[pl + 1];
    acc0.x *= f0; acc0.y *= f0; acc0.z *= f0; acc0.w *= f0;
    acc1.x *= f1; acc1.y *= f1; acc1.z *= f1; acc1.w *= f1;
    *(float4*)&out[((b*HEADS + h)*160 + q0 + pl    )*DH + dd] = acc0;
    *(float4*)&out[((b*HEADS + h)*160 + q0 + pl + 1)*DH + dd] = acc1;
}

// ---------------- K4: attention -----------------------------------------------
__global__ void __launch_bounds__(256, 3) k_attn(const float* __restrict__ memkv) {
    int axial = blockIdx.z, bh = blockIdx.y, qt = blockIdx.x;
    int h = bh & 3, b = bh >> 2;
    const float* Q = g_qkv[3*axial + 0] + (bh*160 + qt*QT)*DH;
    const float* K = g_qkv[3*axial + 1] + bh*160*DH;
    const float* V = g_qkv[3*axial + 2] + bh*160*DH;

    extern __shared__ float dyn[];
    float (*Ks)[36]  = (float(*)[36])(dyn);           // 164x36
    float (*Vs)[36]  = (float(*)[36])(dyn + 5904);    // 164x36
    float (*Qs)[36]  = (float(*)[36])(dyn + 11808);   // 16x36
    float (*S)[168]  = (float(*)[168])(dyn + 12384);  // 16x168
    float* invZ      = dyn + 15072;                   // 16
    float (*Ob)[17]  = (float(*)[17])(dyn + 15088);   // 32x17

    int tid = threadIdx.x, warp = tid >> 5, lane = tid & 31;
    for (int i4 = tid; i4 < 1280; i4 += 256) {
        float4 kv = ((const float4*)K)[i4];
        float4 vv = ((const float4*)V)[i4];
        int r = i4 >> 3, cc = (i4 & 7) * 4;
        *(float4*)&Ks[r][cc] = kv;
        *(float4*)&Vs[r][cc] = vv;
    }
    if (tid < 64) {
        int i4 = tid & 31;
        int r = 160 + (i4 >> 3), cc = (i4 & 7) * 4;
        if (tid < 32) {
            float4 mk = ((const float4*)(memkv + h*NMEM*DH))[i4];
            *(float4*)&Ks[r][cc] = mk;
        } else {
            float4 mv = ((const float4*)(memkv + HEADS*NMEM*DH + h*NMEM*DH))[i4];
            *(float4*)&Vs[r][cc] = mv;
        }
    }
    for (int i4 = tid; i4 < 128; i4 += 256) {
        float4 qv = ((const float4*)Q)[i4];
        int r = i4 >> 3, cc = (i4 & 7) * 4;
        *(float4*)&Qs[r][cc] = qv;
    }
    __syncthreads();

    int qr = warp * 2;
    float s0[6], s1[6];
    #pragma unroll
    for (int j = 0; j < 6; j++) {
        int k = lane + 32*j;
        float a0 = 0.f, a1 = 0.f;
        if (k < 164) {
            #pragma unroll
            for (int d4 = 0; d4 < 8; d4++) {
                float4 kv = *(const float4*)&Ks[k][d4*4];
                float4 qa = *(const float4*)&Qs[qr][d4*4];
                float4 qb = *(const float4*)&Qs[qr+1][d4*4];
                a0 += qa.x*kv.x + qa.y*kv.y + qa.z*kv.z + qa.w*kv.w;
                a1 += qb.x*kv.x + qb.y*kv.y + qb.z*kv.z + qb.w*kv.w;
            }
        }
        s0[j] = a0; s1[j] = a1;
    }
    float mx0 = -1e30f, mx1 = -1e30f;
    #pragma unroll
    for (int j = 0; j < 6; j++)
        if (lane + 32*j < 164) { mx0 = fmaxf(mx0, s0[j]); mx1 = fmaxf(mx1, s1[j]); }
    #pragma unroll
    for (int o = 16; o; o >>= 1) {
        mx0 = fmaxf(mx0, __shfl_xor_sync(0xffffffffu, mx0, o));
        mx1 = fmaxf(mx1, __shfl_xor_sync(0xffffffffu, mx1, o));
    }
    float z0 = 0.f, z1 = 0.f;
    #pragma unroll
    for (int j = 0; j < 6; j++) {
        int k = lane + 32*j;
        if (k < 164) {
            float wgt = (k < 160) ? 160.0f : 1.0f;
            float e0 = __expf(s0[j] - mx0), e1 = __expf(s1[j] - mx1);
            S[qr][k] = e0; S[qr+1][k] = e1;
            z0 += wgt*e0; z1 += wgt*e1;
        }
    }
    #pragma unroll
    for (int o = 16; o; o >>= 1) {
        z0 += __shfl_xor_sync(0xffffffffu, z0, o);
        z1 += __shfl_xor_sync(0xffffffffu, z1, o);
    }
    if (!lane) { invZ[qr] = 1.0f / z0; invZ[qr+1] = 1.0f / z1; }
    __syncwarp();

    float acc0 = 0.f, acc1 = 0.f;
    #pragma unroll 4
    for (int k4 = 0; k4 < 41; k4++) {
        float4 e0 = *(const float4*)&S[qr][k4*4];
        float4 e1 = *(const float4*)&S[qr+1][k4*4];
        float v0 = Vs[k4*4+0][lane], v1 = Vs[k4*4+1][lane];
        float v2 = Vs[k4*4+2][lane], v3 = Vs[k4*4+3][lane];
        acc0 += e0.x*v0 + e0.y*v1 + e0.z*v2 + e0.w*v3;
        acc1 += e1.x*v0 + e1.y*v1 + e1.z*v2 + e1.w*v3;
    }
    Ob[lane][qr]     = acc0 * invZ[qr];
    Ob[lane][qr + 1] = acc1 * invZ[qr + 1];
    __syncthreads();
    float* outp = g_hoT[axial] + (size_t)(b*HID + h*DH)*160 + qt*QT;
    for (int idx = tid; idx < 32*QT; idx += 256) {
        int d = idx >> 4, q = idx & 15;
        outp[d*160 + q] = Ob[d][q];
    }
}

// ---------------- K5: F-GEMM (smem-tiled hoT) + broadcast write --------------
__global__ void __launch_bounds__(320) k_out(float* __restrict__ out) {
    int d0 = blockIdx.x * 4, b = blockIdx.y;
    __shared__ float Es[2][4][128];
    __shared__ __align__(16) float Hs[2][32][164];
    __shared__ __align__(16) float Fsm[2][4][160];
    int t = threadIdx.x;  // 320
    int ax = t / 160, pos = t % 160;
    for (int idx = t; idx < 2*4*128; idx += 320) {
        int a = idx >> 9, dl = (idx >> 7) & 3, hid = idx & 127;
        Es[a][dl][hid] = g_E[a][(d0 + dl)*HID + hid];
    }
    float acc[4] = {0.f, 0.f, 0.f, 0.f};
    for (int h0 = 0; h0 < HID; h0 += 32) {
        __syncthreads();
        for (int idx = t; idx < 2560; idx += 320) {
            int a = idx / 1280, r = (idx % 1280) / 40, p4 = idx % 40;
            *(float4*)&Hs[a][r][p4*4] =
                *(const float4*)(g_hoT[a] + (size_t)(b*HID + h0 + r)*160 + p4*4);
        }
        __syncthreads();
        #pragma unroll 8
        for (int hl = 0; hl < 32; hl++) {
            float hv = Hs[ax][hl][pos];
            #pragma unroll
            for (int dl = 0; dl < 4; dl++) acc[dl] += Es[ax][dl][h0 + hl] * hv;
        }
    }
    #pragma unroll
    for (int dl = 0; dl < 4; dl++) Fsm[ax][dl][pos] = acc[dl] + g_e[ax][d0 + dl];
    __syncthreads();
    int m4 = t % 40, ng = t / 40;   // ng in [0,8)
    #pragma unroll
    for (int dl = 0; dl < 4; dl++) {
        float4 cv = *(const float4*)&Fsm[1][dl][m4*4];
        float* op = out + ((size_t)(b*C + d0 + dl)*160)*160 + m4*4;
        #pragma unroll 5
        for (int i = 0; i < 20; i++) {
            int n = ng + 8*i;
            float r = Fsm[0][dl][n];
            float4 v = {r + cv.x, r + cv.y, r + cv.z, r + cv.w};
            *(float4*)&op[(size_t)n*160] = v;
        }
    }
}

// ---------------- launch --------------------------------------------------------
extern "C" void kernel_launch(void* const* d_in, const int* in_sizes, int n_in,
                              void* d_out, int out_size) {
    const float* x     = (const float*)d_in[0];
    const float* gq    = (const float*)d_in[1];
    const float* gk    = (const float*)d_in[2];
    const float* gv    = (const float*)d_in[3];
    const float* Wq    = (const float*)d_in[4];
    const float* Wk    = (const float*)d_in[5];
    const float* Wv    = (const float*)d_in[6];
    const float* memkv = (const float*)d_in[7];
    const float* Wo    = (const float*)d_in[8];
    const float* bo    = (const float*)d_in[9];
    const float* Wr    = (const float*)d_in[10];
    float* out = (float*)d_out;

    cudaFuncSetAttribute(k_attn, cudaFuncAttributeMaxDynamicSharedMemorySize, 62528);

    k_pre   <<<368, 320>>>(x, Wr, Wo, bo);
    k_reduce<<<B*C, 256>>>(x, gv);
    k_proj  <<<dim3(40, 6), 256>>>(Wq, Wk, Wv, gq, gk);
    k_attn  <<<dim3(10, 16, 2), 256, 62528>>>(memkv);
    k_out   <<<dim3(48, 4), 320>>>(out);
}

// round 7
// speedup vs baseline: 1.3889x; 1.3889x over previous
#include <cuda_runtime.h>
#include <math.h>

#define B 4
#define C 192
#define HEADS 4
#define DH 32
#define HID 128
#define NMEM 4
#define QT 16
#define SQRTC 13.856406460551018f
#define SCALE 0.17677669529663687f

// ---------------- scratch ----------------------------------------------------
__device__ float g_w[B*160*160];
__device__ float g_rowft[B*C*160];
__device__ float g_colft[B*C*160];
__device__ float g_vbr[B*C*160];
__device__ float g_vbc[B*C*160];
__device__ float g_qp[2][2][B*HEADS*160*DH];   // [ksplit][axial]
__device__ float g_kp[2][2][B*HEADS*160*DH];
__device__ float g_vp[2][2][B*HEADS*160*DH];
__device__ float g_hoT[2][B*HID*160];          // [(b*128+hid)*160 + pos]

// ---------------- K1: per-pixel channel norms -> w ---------------------------
__global__ void k_norm(const float* __restrict__ x) {
    int b = blockIdx.x / 160, n = blockIdx.x % 160, m = threadIdx.x;
    const float* xp = x + ((size_t)b*C*160 + n)*160 + m;
    float ss = 0.f;
    #pragma unroll 8
    for (int c = 0; c < C; c++) { float v = xp[(size_t)c*25600]; ss += v*v; }
    g_w[(b*160 + n)*160 + m] = SQRTC / fmaxf(sqrtf(ss), 1e-12f);
}

// ---------------- K2: one pass over x -> row_ft, col_ft, vbr, vbc ------------
__global__ void k_reduce(const float* __restrict__ x, const float* __restrict__ gv) {
    int b = blockIdx.x / C, c = blockIdx.x % C;
    int lane = threadIdx.x & 31, warp = threadIdx.x >> 5;   // 8 warps
    const float* xp = x + (size_t)(b*C + c)*25600;
    const float* wp = g_w + b*25600;
    float gvc = gv[c];
    float colp[5] = {0,0,0,0,0}, vrp[5] = {0,0,0,0,0};
    for (int i = 0; i < 20; i++) {
        int n = warp*20 + i;
        float rs = 0.f, vcs = 0.f;
        #pragma unroll
        for (int mc = 0; mc < 5; mc++) {
            int m = mc*32 + lane;
            float v  = xp[n*160 + m];
            float wv = wp[n*160 + m];
            rs += v; vcs += v*wv;
            colp[mc] += v; vrp[mc] += v*wv;
        }
        #pragma unroll
        for (int o = 16; o; o >>= 1) {
            rs  += __shfl_xor_sync(0xffffffffu, rs,  o);
            vcs += __shfl_xor_sync(0xffffffffu, vcs, o);
        }
        if (!lane) {
            g_rowft[(b*C + c)*160 + n] = rs * (1.0f/160.0f);
            g_vbc  [(b*C + c)*160 + n] = gvc * vcs;
        }
    }
    __shared__ float scol[8][160], svr[8][160];
    #pragma unroll
    for (int mc = 0; mc < 5; mc++) {
        scol[warp][mc*32 + lane] = colp[mc];
        svr [warp][mc*32 + lane] = vrp[mc];
    }
    __syncthreads();
    if (threadIdx.x < 160) {
        int m = threadIdx.x;
        float cs = 0.f, vr = 0.f;
        #pragma unroll
        for (int w2 = 0; w2 < 8; w2++) { cs += scol[w2][m]; vr += svr[w2][m]; }
        g_colft[(b*C + c)*160 + m] = cs * (1.0f/160.0f);
        g_vbr  [(b*C + c)*160 + m] = gvc * vr;
    }
}

// ---------------- K3: projections, split-K=2, norms inline -------------------
__global__ void __launch_bounds__(256) k_proj(
        const float* __restrict__ Wq, const float* __restrict__ Wk,
        const float* __restrict__ Wv, const float* __restrict__ gq,
        const float* __restrict__ gk) {
    int which = blockIdx.y, z = blockIdx.z;
    int p0 = blockIdx.x * 32;
    int b = p0 / 160, q0 = p0 % 160;
    const float *src, *W, *gvec = 0;
    float* out; float factor = 1.f;
    switch (which) {
        case 0: src=g_rowft; W=Wq; gvec=gq; out=g_qp[z][0]; factor=SCALE*SQRTC; break;
        case 1: src=g_colft; W=Wk; gvec=gk; out=g_kp[z][0]; factor=SQRTC;       break;
        case 2: src=g_vbr;   W=Wv;          out=g_vp[z][0];                     break;
        case 3: src=g_colft; W=Wq; gvec=gq; out=g_qp[z][1]; factor=SCALE*SQRTC; break;
        case 4: src=g_rowft; W=Wk; gvec=gk; out=g_kp[z][1]; factor=SQRTC;       break;
        default:src=g_vbc;   W=Wv;          out=g_vp[z][1];                     break;
    }
    __shared__ __align__(16) float Xs[192][36];
    __shared__ __align__(16) float Wsm[32][132];
    __shared__ float red[8][32];
    __shared__ float fs[32];
    int t = threadIdx.x;
    for (int idx = t; idx < 192*32; idx += 256) {
        int c = idx >> 5, pp = idx & 31;
        Xs[c][pp] = src[(b*C + c)*160 + q0 + pp];
    }
    __syncthreads();
    if (gvec) {
        int p = t & 31, cg = t >> 5;
        float ssp = 0.f;
        #pragma unroll 4
        for (int c = cg; c < 192; c += 8) { float v = Xs[c][p]; ssp += v*v; }
        red[cg][p] = ssp;
    }
    __syncthreads();
    if (t < 32) {
        if (gvec) {
            float ss = 0.f;
            #pragma unroll
            for (int j = 0; j < 8; j++) ss += red[j][t];
            fs[t] = factor / fmaxf(sqrtf(ss), 1e-12f);
        } else fs[t] = 1.f;
    }
    int d0 = (t & 31) * 4, pl = (t >> 5) * 4;
    float4 acc0 = {0,0,0,0}, acc1 = {0,0,0,0}, acc2 = {0,0,0,0}, acc3 = {0,0,0,0};
    int cbase = z * 96;
    for (int cc0 = 0; cc0 < 96; cc0 += 32) {
        int c0 = cbase + cc0;
        __syncthreads();
        for (int idx = t; idx < 32*128; idx += 256) {
            int dim = idx >> 5, k = idx & 31;
            float wv = W[dim*C + c0 + k];
            if (gvec) wv *= gvec[c0 + k];
            Wsm[k][dim] = wv;
        }
        __syncthreads();
        #pragma unroll
        for (int k = 0; k < 32; k++) {
            float4 wv = *(const float4*)&Wsm[k][d0];
            float4 xv = *(const float4*)&Xs[c0 + k][pl];
            acc0.x += wv.x*xv.x; acc0.y += wv.y*xv.x; acc0.z += wv.z*xv.x; acc0.w += wv.w*xv.x;
            acc1.x += wv.x*xv.y; acc1.y += wv.y*xv.y; acc1.z += wv.z*xv.y; acc1.w += wv.w*xv.y;
            acc2.x += wv.x*xv.z; acc2.y += wv.y*xv.z; acc2.z += wv.z*xv.z; acc2.w += wv.w*xv.z;
            acc3.x += wv.x*xv.w; acc3.y += wv.y*xv.w; acc3.z += wv.z*xv.w; acc3.w += wv.w*xv.w;
        }
    }
    int h = d0 >> 5, dd = d0 & 31;
    float4 accs[4] = {acc0, acc1, acc2, acc3};
    #pragma unroll
    for (int pg = 0; pg < 4; pg++) {
        float f = fs[pl + pg];
        float4 v = accs[pg];
        v.x *= f; v.y *= f; v.z *= f; v.w *= f;
        *(float4*)&out[((b*HEADS + h)*160 + q0 + pl + pg)*DH + dd] = v;
    }
}

// ---------------- K4: attention (fast variant, merge-on-load) ----------------
__global__ void __launch_bounds__(256, 3) k_attn(const float* __restrict__ memkv) {
    int axial = blockIdx.z, bh = blockIdx.y, qt = blockIdx.x;
    int h = bh & 3, b = bh >> 2;
    const float* Q0 = g_qp[0][axial] + (bh*160 + qt*QT)*DH;
    const float* Q1 = g_qp[1][axial] + (bh*160 + qt*QT)*DH;
    const float* K0 = g_kp[0][axial] + bh*160*DH;
    const float* K1 = g_kp[1][axial] + bh*160*DH;
    const float* V0 = g_vp[0][axial] + bh*160*DH;
    const float* V1 = g_vp[1][axial] + bh*160*DH;

    extern __shared__ float dyn[];
    float (*Ks)[36]  = (float(*)[36])(dyn);           // 164x36
    float (*Vs)[36]  = (float(*)[36])(dyn + 5904);    // 164x36
    float (*Qs)[36]  = (float(*)[36])(dyn + 11808);   // 16x36
    float (*S)[168]  = (float(*)[168])(dyn + 12384);  // 16x168
    float* invZ      = dyn + 15072;                   // 16
    float (*Ob)[17]  = (float(*)[17])(dyn + 15088);   // 32x17

    int tid = threadIdx.x, warp = tid >> 5, lane = tid & 31;
    for (int i4 = tid; i4 < 1280; i4 += 256) {
        float4 ka = ((const float4*)K0)[i4], kb = ((const float4*)K1)[i4];
        float4 va = ((const float4*)V0)[i4], vb = ((const float4*)V1)[i4];
        int r = i4 >> 3, cc = (i4 & 7) * 4;
        float4 kv = {ka.x+kb.x, ka.y+kb.y, ka.z+kb.z, ka.w+kb.w};
        float4 vv = {va.x+vb.x, va.y+vb.y, va.z+vb.z, va.w+vb.w};
        *(float4*)&Ks[r][cc] = kv;
        *(float4*)&Vs[r][cc] = vv;
    }
    if (tid < 64) {
        int i4 = tid & 31;
        int r = 160 + (i4 >> 3), cc = (i4 & 7) * 4;
        if (tid < 32) {
            float4 mk = ((const float4*)(memkv + h*NMEM*DH))[i4];
            *(float4*)&Ks[r][cc] = mk;
        } else {
            float4 mv = ((const float4*)(memkv + HEADS*NMEM*DH + h*NMEM*DH))[i4];
            *(float4*)&Vs[r][cc] = mv;
        }
    }
    for (int i4 = tid; i4 < 128; i4 += 256) {
        float4 qa = ((const float4*)Q0)[i4], qb = ((const float4*)Q1)[i4];
        int r = i4 >> 3, cc = (i4 & 7) * 4;
        float4 qv = {qa.x+qb.x, qa.y+qb.y, qa.z+qb.z, qa.w+qb.w};
        *(float4*)&Qs[r][cc] = qv;
    }
    __syncthreads();

    int qr = warp * 2;
    float s0[6], s1[6];
    #pragma unroll
    for (int j = 0; j < 6; j++) {
        int k = lane + 32*j;
        float a0 = 0.f, a1 = 0.f;
        if (k < 164) {
            #pragma unroll
            for (int d4 = 0; d4 < 8; d4++) {
                float4 kv = *(const float4*)&Ks[k][d4*4];
                float4 qa = *(const float4*)&Qs[qr][d4*4];
                float4 qb = *(const float4*)&Qs[qr+1][d4*4];
                a0 += qa.x*kv.x + qa.y*kv.y + qa.z*kv.z + qa.w*kv.w;
                a1 += qb.x*kv.x + qb.y*kv.y + qb.z*kv.z + qb.w*kv.w;
            }
        }
        s0[j] = a0; s1[j] = a1;
    }
    float mx0 = -1e30f, mx1 = -1e30f;
    #pragma unroll
    for (int j = 0; j < 6; j++)
        if (lane + 32*j < 164) { mx0 = fmaxf(mx0, s0[j]); mx1 = fmaxf(mx1, s1[j]); }
    #pragma unroll
    for (int o = 16; o; o >>= 1) {
        mx0 = fmaxf(mx0, __shfl_xor_sync(0xffffffffu, mx0, o));
        mx1 = fmaxf(mx1, __shfl_xor_sync(0xffffffffu, mx1, o));
    }
    float z0 = 0.f, z1 = 0.f;
    #pragma unroll
    for (int j = 0; j < 6; j++) {
        int k = lane + 32*j;
        if (k < 164) {
            float wgt = (k < 160) ? 160.0f : 1.0f;
            float e0 = __expf(s0[j] - mx0), e1 = __expf(s1[j] - mx1);
            S[qr][k] = e0; S[qr+1][k] = e1;
            z0 += wgt*e0; z1 += wgt*e1;
        }
    }
    #pragma unroll
    for (int o = 16; o; o >>= 1) {
        z0 += __shfl_xor_sync(0xffffffffu, z0, o);
        z1 += __shfl_xor_sync(0xffffffffu, z1, o);
    }
    if (!lane) { invZ[qr] = 1.0f / z0; invZ[qr+1] = 1.0f / z1; }
    __syncwarp();

    float acc0 = 0.f, acc1 = 0.f;
    #pragma unroll 4
    for (int k4 = 0; k4 < 41; k4++) {
        float4 e0 = *(const float4*)&S[qr][k4*4];
        float4 e1 = *(const float4*)&S[qr+1][k4*4];
        float v0 = Vs[k4*4+0][lane], v1 = Vs[k4*4+1][lane];
        float v2 = Vs[k4*4+2][lane], v3 = Vs[k4*4+3][lane];
        acc0 += e0.x*v0 + e0.y*v1 + e0.z*v2 + e0.w*v3;
        acc1 += e1.x*v0 + e1.y*v1 + e1.z*v2 + e1.w*v3;
    }
    Ob[lane][qr]     = acc0 * invZ[qr];
    Ob[lane][qr + 1] = acc1 * invZ[qr + 1];
    __syncthreads();
    float* outp = g_hoT[axial] + (size_t)(b*HID + h*DH)*160 + qt*QT;
    for (int idx = tid; idx < 32*QT; idx += 256) {
        int d = idx >> 4, q = idx & 15;
        outp[d*160 + q] = Ob[d][q];
    }
}

// ---------------- K5: fold + E-GEMM + broadcast write (R3 verbatim) ----------
__global__ void k_final(const float* __restrict__ Wr, const float* __restrict__ Wo,
                        const float* __restrict__ bo, float* __restrict__ out) {
    int d0 = blockIdx.x * 2, b = blockIdx.y;
    __shared__ float Wr4[4][192];                 // r = ax*2+dl
    __shared__ float Es[4][128];
    __shared__ float eb[4];
    __shared__ __align__(16) float Frs[2][160], Fcs[2][160];
    int t = threadIdx.x;  // 160
    for (int idx = t; idx < 4*192; idx += 160) {
        int r = idx / 192, c = idx % 192;
        Wr4[r][c] = Wr[(d0 + (r & 1))*2*C + (r >> 1)*C + c];
    }
    __syncthreads();
    if (t < 128) {
        float a0 = 0, a1 = 0, a2 = 0, a3 = 0;
        #pragma unroll 4
        for (int c = 0; c < 192; c++) {
            float wo = Wo[c*HID + t];
            a0 += Wr4[0][c]*wo; a1 += Wr4[1][c]*wo;
            a2 += Wr4[2][c]*wo; a3 += Wr4[3][c]*wo;
        }
        Es[0][t] = a0; Es[1][t] = a1; Es[2][t] = a2; Es[3][t] = a3;
    } else if (t < 132) {
        int r = t - 128; float e = 0.f;
        for (int c = 0; c < 192; c++) e += Wr4[r][c] * bo[c];
        eb[r] = e;
    }
    __syncthreads();
    {
        const float* hr = g_hoT[0] + (size_t)b*HID*160 + t;
        const float* hc = g_hoT[1] + (size_t)b*HID*160 + t;
        float fr0 = 0, fr1 = 0, fc0 = 0, fc1 = 0;
        #pragma unroll 4
        for (int hid = 0; hid < HID; hid++) {
            float a  = hr[hid*160];
            float bb = hc[hid*160];
            fr0 += Es[0][hid]*a;  fr1 += Es[1][hid]*a;
            fc0 += Es[2][hid]*bb; fc1 += Es[3][hid]*bb;
        }
        Frs[0][t] = fr0 + eb[0]; Frs[1][t] = fr1 + eb[1];
        Fcs[0][t] = fc0 + eb[2]; Fcs[1][t] = fc1 + eb[3];
    }
    __syncthreads();
    int m4 = t % 40, nb = t / 40;
    #pragma unroll
    for (int dl = 0; dl < 2; dl++) {
        float4 cv = *(const float4*)&Fcs[dl][m4*4];
        float* op = out + ((size_t)(b*C + d0 + dl)*160)*160 + m4*4;
        #pragma unroll 8
        for (int i = 0; i < 40; i++) {
            int n = nb + 4*i;
            float r = Frs[dl][n];
            float4 v = {r + cv.x, r + cv.y, r + cv.z, r + cv.w};
            *(float4*)&op[(size_t)n*160] = v;
        }
    }
}

// ---------------- launch ------------------------------------------------------
extern "C" void kernel_launch(void* const* d_in, const int* in_sizes, int n_in,
                              void* d_out, int out_size) {
    const float* x     = (const float*)d_in[0];
    const float* gq    = (const float*)d_in[1];
    const float* gk    = (const float*)d_in[2];
    const float* gv    = (const float*)d_in[3];
    const float* Wq    = (const float*)d_in[4];
    const float* Wk    = (const float*)d_in[5];
    const float* Wv    = (const float*)d_in[6];
    const float* memkv = (const float*)d_in[7];
    const float* Wo    = (const float*)d_in[8];
    const float* bo    = (const float*)d_in[9];
    const float* Wr    = (const float*)d_in[10];
    float* out = (float*)d_out;

    cudaFuncSetAttribute(k_attn, cudaFuncAttributeMaxDynamicSharedMemorySize, 62528);

    k_norm  <<<B*160, 160>>>(x);
    k_reduce<<<B*C, 256>>>(x, gv);
    k_proj  <<<dim3(20, 6, 2), 256>>>(Wq, Wk, Wv, gq, gk);
    k_attn  <<<dim3(10, 16, 2), 256, 62528>>>(memkv);
    k_final <<<dim3(96, 4), 160>>>(Wr, Wo, bo, out);
}

// round 8
// speedup vs baseline: 1.4335x; 1.0321x over previous
#include <cuda_runtime.h>
#include <math.h>

#define B 4
#define C 192
#define HEADS 4
#define DH 32
#define HID 128
#define NMEM 4
#define QT 16
#define SQRTC 13.856406460551018f
#define SCALE 0.17677669529663687f

// ---------------- scratch ----------------------------------------------------
__device__ float g_w[B*160*160];
__device__ float g_rowft[B*C*160];
__device__ float g_colft[B*C*160];
__device__ float g_vbr[B*C*160];
__device__ float g_vbc[B*C*160];
__device__ float g_qp[2][2][B*HEADS*160*DH];   // [ksplit][axial]
__device__ float g_kp[2][2][B*HEADS*160*DH];
__device__ float g_vp[2][2][B*HEADS*160*DH];
__device__ float g_hoT[2][B*HID*160];          // [(b*128+hid)*160 + pos]

// ---------------- K1: per-pixel channel norms -> w (warp-per-channel-slice) --
__global__ void __launch_bounds__(256) k_norm(const float* __restrict__ x) {
    int b = blockIdx.x / 160, n = blockIdx.x % 160;
    int lane = threadIdx.x & 31, warp = threadIdx.x >> 5;   // 8 warps
    const float4* xp4 = (const float4*)(x + ((size_t)b*C*160 + n)*160);
    float4 ssA = {0,0,0,0}, ssB = {0,0,0,0};
    #pragma unroll 4
    for (int c = warp; c < C; c += 8) {
        const float4* row = xp4 + (size_t)c*6400;
        float4 va = row[lane];
        ssA.x += va.x*va.x; ssA.y += va.y*va.y; ssA.z += va.z*va.z; ssA.w += va.w*va.w;
        if (lane < 8) {
            float4 vb = row[32 + lane];
            ssB.x += vb.x*vb.x; ssB.y += vb.y*vb.y; ssB.z += vb.z*vb.z; ssB.w += vb.w*vb.w;
        }
    }
    __shared__ __align__(16) float red[8][160];
    *(float4*)&red[warp][lane*4] = ssA;
    if (lane < 8) *(float4*)&red[warp][128 + lane*4] = ssB;
    __syncthreads();
    if (threadIdx.x < 160) {
        int m = threadIdx.x;
        float ss = 0.f;
        #pragma unroll
        for (int w2 = 0; w2 < 8; w2++) ss += red[w2][m];
        g_w[(b*160 + n)*160 + m] = SQRTC / fmaxf(sqrtf(ss), 1e-12f);
    }
}

// ---------------- K2: one pass over x -> row_ft, col_ft, vbr, vbc ------------
__global__ void k_reduce(const float* __restrict__ x, const float* __restrict__ gv) {
    int b = blockIdx.x / C, c = blockIdx.x % C;
    int lane = threadIdx.x & 31, warp = threadIdx.x >> 5;   // 8 warps
    const float* xp = x + (size_t)(b*C + c)*25600;
    const float* wp = g_w + b*25600;
    float gvc = gv[c];
    float colp[5] = {0,0,0,0,0}, vrp[5] = {0,0,0,0,0};
    for (int i = 0; i < 20; i++) {
        int n = warp*20 + i;
        float rs = 0.f, vcs = 0.f;
        #pragma unroll
        for (int mc = 0; mc < 5; mc++) {
            int m = mc*32 + lane;
            float v  = xp[n*160 + m];
            float wv = wp[n*160 + m];
            rs += v; vcs += v*wv;
            colp[mc] += v; vrp[mc] += v*wv;
        }
        #pragma unroll
        for (int o = 16; o; o >>= 1) {
            rs  += __shfl_xor_sync(0xffffffffu, rs,  o);
            vcs += __shfl_xor_sync(0xffffffffu, vcs, o);
        }
        if (!lane) {
            g_rowft[(b*C + c)*160 + n] = rs * (1.0f/160.0f);
            g_vbc  [(b*C + c)*160 + n] = gvc * vcs;
        }
    }
    __shared__ float scol[8][160], svr[8][160];
    #pragma unroll
    for (int mc = 0; mc < 5; mc++) {
        scol[warp][mc*32 + lane] = colp[mc];
        svr [warp][mc*32 + lane] = vrp[mc];
    }
    __syncthreads();
    if (threadIdx.x < 160) {
        int m = threadIdx.x;
        float cs = 0.f, vr = 0.f;
        #pragma unroll
        for (int w2 = 0; w2 < 8; w2++) { cs += scol[w2][m]; vr += svr[w2][m]; }
        g_colft[(b*C + c)*160 + m] = cs * (1.0f/160.0f);
        g_vbr  [(b*C + c)*160 + m] = gvc * vr;
    }
}

// ---------------- K3: projections, split-K=2, norms inline -------------------
__global__ void __launch_bounds__(256) k_proj(
        const float* __restrict__ Wq, const float* __restrict__ Wk,
        const float* __restrict__ Wv, const float* __restrict__ gq,
        const float* __restrict__ gk) {
    int which = blockIdx.y, z = blockIdx.z;
    int p0 = blockIdx.x * 32;
    int b = p0 / 160, q0 = p0 % 160;
    const float *src, *W, *gvec = 0;
    float* out; float factor = 1.f;
    switch (which) {
        case 0: src=g_rowft; W=Wq; gvec=gq; out=g_qp[z][0]; factor=SCALE*SQRTC; break;
        case 1: src=g_colft; W=Wk; gvec=gk; out=g_kp[z][0]; factor=SQRTC;       break;
        case 2: src=g_vbr;   W=Wv;          out=g_vp[z][0];                     break;
        case 3: src=g_colft; W=Wq; gvec=gq; out=g_qp[z][1]; factor=SCALE*SQRTC; break;
        case 4: src=g_rowft; W=Wk; gvec=gk; out=g_kp[z][1]; factor=SQRTC;       break;
        default:src=g_vbc;   W=Wv;          out=g_vp[z][1];                     break;
    }
    __shared__ __align__(16) float Xs[192][36];
    __shared__ __align__(16) float Wsm[32][132];
    __shared__ float red[8][32];
    __shared__ float fs[32];
    int t = threadIdx.x;
    for (int idx = t; idx < 192*32; idx += 256) {
        int c = idx >> 5, pp = idx & 31;
        Xs[c][pp] = src[(b*C + c)*160 + q0 + pp];
    }
    __syncthreads();
    if (gvec) {
        int p = t & 31, cg = t >> 5;
        float ssp = 0.f;
        #pragma unroll 4
        for (int c = cg; c < 192; c += 8) { float v = Xs[c][p]; ssp += v*v; }
        red[cg][p] = ssp;
    }
    __syncthreads();
    if (t < 32) {
        if (gvec) {
            float ss = 0.f;
            #pragma unroll
            for (int j = 0; j < 8; j++) ss += red[j][t];
            fs[t] = factor / fmaxf(sqrtf(ss), 1e-12f);
        } else fs[t] = 1.f;
    }
    int d0 = (t & 31) * 4, pl = (t >> 5) * 4;
    float4 acc0 = {0,0,0,0}, acc1 = {0,0,0,0}, acc2 = {0,0,0,0}, acc3 = {0,0,0,0};
    int cbase = z * 96;
    for (int cc0 = 0; cc0 < 96; cc0 += 32) {
        int c0 = cbase + cc0;
        __syncthreads();
        for (int idx = t; idx < 32*128; idx += 256) {
            int dim = idx >> 5, k = idx & 31;
            float wv = W[dim*C + c0 + k];
            if (gvec) wv *= gvec[c0 + k];
            Wsm[k][dim] = wv;
        }
        __syncthreads();
        #pragma unroll
        for (int k = 0; k < 32; k++) {
            float4 wv = *(const float4*)&Wsm[k][d0];
            float4 xv = *(const float4*)&Xs[c0 + k][pl];
            acc0.x += wv.x*xv.x; acc0.y += wv.y*xv.x; acc0.z += wv.z*xv.x; acc0.w += wv.w*xv.x;
            acc1.x += wv.x*xv.y; acc1.y += wv.y*xv.y; acc1.z += wv.z*xv.y; acc1.w += wv.w*xv.y;
            acc2.x += wv.x*xv.z; acc2.y += wv.y*xv.z; acc2.z += wv.z*xv.z; acc2.w += wv.w*xv.z;
            acc3.x += wv.x*xv.w; acc3.y += wv.y*xv.w; acc3.z += wv.z*xv.w; acc3.w += wv.w*xv.w;
        }
    }
    int h = d0 >> 5, dd = d0 & 31;
    float4 accs[4] = {acc0, acc1, acc2, acc3};
    #pragma unroll
    for (int pg = 0; pg < 4; pg++) {
        float f = fs[pl + pg];
        float4 v = accs[pg];
        v.x *= f; v.y *= f; v.z *= f; v.w *= f;
        *(float4*)&out[((b*HEADS + h)*160 + q0 + pl + pg)*DH + dd] = v;
    }
}

// ---------------- K4: attention (fast variant, merge-on-load) ----------------
__global__ void __launch_bounds__(256, 3) k_attn(const float* __restrict__ memkv) {
    int axial = blockIdx.z, bh = blockIdx.y, qt = blockIdx.x;
    int h = bh & 3, b = bh >> 2;
    const float* Q0 = g_qp[0][axial] + (bh*160 + qt*QT)*DH;
    const float* Q1 = g_qp[1][axial] + (bh*160 + qt*QT)*DH;
    const float* K0 = g_kp[0][axial] + bh*160*DH;
    const float* K1 = g_kp[1][axial] + bh*160*DH;
    const float* V0 = g_vp[0][axial] + bh*160*DH;
    const float* V1 = g_vp[1][axial] + bh*160*DH;

    extern __shared__ float dyn[];
    float (*Ks)[36]  = (float(*)[36])(dyn);           // 164x36
    float (*Vs)[36]  = (float(*)[36])(dyn + 5904);    // 164x36
    float (*Qs)[36]  = (float(*)[36])(dyn + 11808);   // 16x36
    float (*S)[168]  = (float(*)[168])(dyn + 12384);  // 16x168
    float* invZ      = dyn + 15072;                   // 16
    float (*Ob)[17]  = (float(*)[17])(dyn + 15088);   // 32x17

    int tid = threadIdx.x, warp = tid >> 5, lane = tid & 31;
    for (int i4 = tid; i4 < 1280; i4 += 256) {
        float4 ka = ((const float4*)K0)[i4], kb = ((const float4*)K1)[i4];
        float4 va = ((const float4*)V0)[i4], vb = ((const float4*)V1)[i4];
        int r = i4 >> 3, cc = (i4 & 7) * 4;
        float4 kv = {ka.x+kb.x, ka.y+kb.y, ka.z+kb.z, ka.w+kb.w};
        float4 vv = {va.x+vb.x, va.y+vb.y, va.z+vb.z, va.w+vb.w};
        *(float4*)&Ks[r][cc] = kv;
        *(float4*)&Vs[r][cc] = vv;
    }
    if (tid < 64) {
        int i4 = tid & 31;
        int r = 160 + (i4 >> 3), cc = (i4 & 7) * 4;
        if (tid < 32) {
            float4 mk = ((const float4*)(memkv + h*NMEM*DH))[i4];
            *(float4*)&Ks[r][cc] = mk;
        } else {
            float4 mv = ((const float4*)(memkv + HEADS*NMEM*DH + h*NMEM*DH))[i4];
            *(float4*)&Vs[r][cc] = mv;
        }
    }
    for (int i4 = tid; i4 < 128; i4 += 256) {
        float4 qa = ((const float4*)Q0)[i4], qb = ((const float4*)Q1)[i4];
        int r = i4 >> 3, cc = (i4 & 7) * 4;
        float4 qv = {qa.x+qb.x, qa.y+qb.y, qa.z+qb.z, qa.w+qb.w};
        *(float4*)&Qs[r][cc] = qv;
    }
    __syncthreads();

    int qr = warp * 2;
    float s0[6], s1[6];
    #pragma unroll
    for (int j = 0; j < 6; j++) {
        int k = lane + 32*j;
        float a0 = 0.f, a1 = 0.f;
        if (k < 164) {
            #pragma unroll
            for (int d4 = 0; d4 < 8; d4++) {
                float4 kv = *(const float4*)&Ks[k][d4*4];
                float4 qa = *(const float4*)&Qs[qr][d4*4];
                float4 qb = *(const float4*)&Qs[qr+1][d4*4];
                a0 += qa.x*kv.x + qa.y*kv.y + qa.z*kv.z + qa.w*kv.w;
                a1 += qb.x*kv.x + qb.y*kv.y + qb.z*kv.z + qb.w*kv.w;
            }
        }
        s0[j] = a0; s1[j] = a1;
    }
    float mx0 = -1e30f, mx1 = -1e30f;
    #pragma unroll
    for (int j = 0; j < 6; j++)
        if (lane + 32*j < 164) { mx0 = fmaxf(mx0, s0[j]); mx1 = fmaxf(mx1, s1[j]); }
    #pragma unroll
    for (int o = 16; o; o >>= 1) {
        mx0 = fmaxf(mx0, __shfl_xor_sync(0xffffffffu, mx0, o));
        mx1 = fmaxf(mx1, __shfl_xor_sync(0xffffffffu, mx1, o));
    }
    float z0 = 0.f, z1 = 0.f;
    #pragma unroll
    for (int j = 0; j < 6; j++) {
        int k = lane + 32*j;
        if (k < 164) {
            float wgt = (k < 160) ? 160.0f : 1.0f;
            float e0 = __expf(s0[j] - mx0), e1 = __expf(s1[j] - mx1);
            S[qr][k] = e0; S[qr+1][k] = e1;
            z0 += wgt*e0; z1 += wgt*e1;
        }
    }
    #pragma unroll
    for (int o = 16; o; o >>= 1) {
        z0 += __shfl_xor_sync(0xffffffffu, z0, o);
        z1 += __shfl_xor_sync(0xffffffffu, z1, o);
    }
    if (!lane) { invZ[qr] = 1.0f / z0; invZ[qr+1] = 1.0f / z1; }
    __syncwarp();

    float acc0 = 0.f, acc1 = 0.f;
    #pragma unroll 4
    for (int k4 = 0; k4 < 41; k4++) {
        float4 e0 = *(const float4*)&S[qr][k4*4];
        float4 e1 = *(const float4*)&S[qr+1][k4*4];
        float v0 = Vs[k4*4+0][lane], v1 = Vs[k4*4+1][lane];
        float v2 = Vs[k4*4+2][lane], v3 = Vs[k4*4+3][lane];
        acc0 += e0.x*v0 + e0.y*v1 + e0.z*v2 + e0.w*v3;
        acc1 += e1.x*v0 + e1.y*v1 + e1.z*v2 + e1.w*v3;
    }
    Ob[lane][qr]     = acc0 * invZ[qr];
    Ob[lane][qr + 1] = acc1 * invZ[qr + 1];
    __syncthreads();
    float* outp = g_hoT[axial] + (size_t)(b*HID + h*DH)*160 + qt*QT;
    for (int idx = tid; idx < 32*QT; idx += 256) {
        int d = idx >> 4, q = idx & 15;
        outp[d*160 + q] = Ob[d][q];
    }
}

// ---------------- K5: fold + E-GEMM + broadcast write (320 threads) ----------
__global__ void __launch_bounds__(320) k_final(
        const float* __restrict__ Wr, const float* __restrict__ Wo,
        const float* __restrict__ bo, float* __restrict__ out) {
    int d0 = blockIdx.x * 2, b = blockIdx.y;
    __shared__ float Wr4[4][192];                 // r = ax*2+dl
    __shared__ float Es[4][128];
    __shared__ float eb[4];
    __shared__ __align__(16) float Frs[2][160], Fcs[2][160];
    int t = threadIdx.x;  // 320
    for (int idx = t; idx < 4*192; idx += 320) {
        int r = idx / 192, c = idx % 192;
        Wr4[r][c] = Wr[(d0 + (r & 1))*2*C + (r >> 1)*C + c];
    }
    __syncthreads();
    if (t < 256) {
        int tt = t & 127, pr = t >> 7;     // pr 0: Es[0],Es[1];  pr 1: Es[2],Es[3]
        float a0 = 0, a1 = 0;
        #pragma unroll 4
        for (int c = 0; c < 192; c++) {
            float wo = Wo[c*HID + tt];
            a0 += Wr4[pr*2    ][c]*wo;
            a1 += Wr4[pr*2 + 1][c]*wo;
        }
        Es[pr*2][tt] = a0; Es[pr*2 + 1][tt] = a1;
    } else if (t < 260) {
        int r = t - 256; float e = 0.f;
        for (int c = 0; c < 192; c++) e += Wr4[r][c] * bo[c];
        eb[r] = e;
    }
    __syncthreads();
    {
        int pos = t % 160, side = t / 160;     // side 0: Fr, side 1: Fc
        const float* hp = g_hoT[side] + (size_t)b*HID*160 + pos;
        float f0 = 0, f1 = 0;
        #pragma unroll 4
        for (int hid = 0; hid < HID; hid++) {
            float a = hp[hid*160];
            f0 += Es[side*2    ][hid]*a;
            f1 += Es[side*2 + 1][hid]*a;
        }
        if (side == 0) { Frs[0][pos] = f0 + eb[0]; Frs[1][pos] = f1 + eb[1]; }
        else           { Fcs[0][pos] = f0 + eb[2]; Fcs[1][pos] = f1 + eb[3]; }
    }
    __syncthreads();
    int m4 = t % 40, nb = t / 40;     // nb in [0,8)
    #pragma unroll
    for (int dl = 0; dl < 2; dl++) {
        float4 cv = *(const float4*)&Fcs[dl][m4*4];
        float* op = out + ((size_t)(b*C + d0 + dl)*160)*160 + m4*4;
        #pragma unroll 5
        for (int i = 0; i < 20; i++) {
            int n = nb + 8*i;
            float r = Frs[dl][n];
            float4 v = {r + cv.x, r + cv.y, r + cv.z, r + cv.w};
            *(float4*)&op[(size_t)n*160] = v;
        }
    }
}

// ---------------- launch ------------------------------------------------------
extern "C" void kernel_launch(void* const* d_in, const int* in_sizes, int n_in,
                              void* d_out, int out_size) {
    const float* x     = (const float*)d_in[0];
    const float* gq    = (const float*)d_in[1];
    const float* gk    = (const float*)d_in[2];
    const float* gv    = (const float*)d_in[3];
    const float* Wq    = (const float*)d_in[4];
    const float* Wk    = (const float*)d_in[5];
    const float* Wv    = (const float*)d_in[6];
    const float* memkv = (const float*)d_in[7];
    const float* Wo    = (const float*)d_in[8];
    const float* bo    = (const float*)d_in[9];
    const float* Wr    = (const float*)d_in[10];
    float* out = (float*)d_out;

    cudaFuncSetAttribute(k_attn, cudaFuncAttributeMaxDynamicSharedMemorySize, 62528);

    k_norm  <<<B*160, 256>>>(x);
    k_reduce<<<B*C, 256>>>(x, gv);
    k_proj  <<<dim3(20, 6, 2), 256>>>(Wq, Wk, Wv, gq, gk);
    k_attn  <<<dim3(10, 16, 2), 256, 62528>>>(memkv);
    k_final <<<dim3(96, 4), 320>>>(Wr, Wo, bo, out);
}